// round 1
// baseline (speedup 1.0000x reference)
#include <cuda_runtime.h>
#include <math.h>

// Problem constants (reference: DIM=1024, VOCAB=50257; vocab passed dynamically).
#define DIM   1024
#define BLOCK 256
#define NWARP (BLOCK / 32)          // 8 warps per CTA
#define GRID  (DIM / NWARP)         // 128 CTAs, one warp per output row

// Scratch: z vector + completion ticket (no device allocation allowed).
__device__ float        g_z[DIM];
__device__ unsigned int g_count = 0;

__global__ __launch_bounds__(BLOCK, 1)
void embed_fused_kernel(const float* __restrict__ filters,
                        const float* __restrict__ w_t,
                        const float* __restrict__ w_h,
                        float*       __restrict__ out,
                        int vocab)
{
    __shared__ float s_y[DIM];
    __shared__ float s_max[NWARP];
    __shared__ float s_sum[NWARP];
    __shared__ int   s_last;

    const int tid  = threadIdx.x;
    const int lane = tid & 31;
    const int warp = tid >> 5;

    // ---- Phase 1: y_k = relu(filters[:,0]) except last element -------------
    // 1024 scattered 4B loads (stride = vocab floats). Redundant per CTA but
    // L2-resident after the first wave.
    for (int j = tid; j < DIM; j += BLOCK) {
        float v = filters[(size_t)j * (size_t)vocab];
        s_y[j] = (j == DIM - 1) ? v : fmaxf(v, 0.0f);
    }
    __syncthreads();

    // ---- Phase 2: one warp per row, both mat-vecs fused ---------------------
    const int row = blockIdx.x * NWARP + warp;   // 0..1023

    const float4* __restrict__ wt4 = (const float4*)(w_t + (size_t)row * DIM);
    const float4* __restrict__ wh4 = (const float4*)(w_h + (size_t)row * DIM);
    const float4* __restrict__ y4  = (const float4*)s_y;

    float dt = 0.0f, dh = 0.0f;
    #pragma unroll
    for (int k = 0; k < DIM / (4 * 32); ++k) {   // 8 iterations
        const int idx = k * 32 + lane;
        const float4 a = wt4[idx];
        const float4 b = wh4[idx];
        const float4 y = y4[idx];
        dt += a.x * y.x + a.y * y.y + a.z * y.z + a.w * y.w;
        dh += b.x * y.x + b.y * y.y + b.z * y.z + b.w * y.w;
    }
    #pragma unroll
    for (int o = 16; o > 0; o >>= 1) {
        dt += __shfl_xor_sync(0xffffffffu, dt, o);
        dh += __shfl_xor_sync(0xffffffffu, dh, o);
    }
    if (lane == 0) {
        const float t = 1.0f / (1.0f + expf(-dt));   // sigmoid
        const float g = fmaxf(dh, 0.0f);             // relu
        g_z[row] = t * g + (1.0f - t) * s_y[row];
    }

    // ---- Phase 3: last CTA does log_softmax ---------------------------------
    __threadfence();          // make g_z writes visible device-wide
    __syncthreads();          // all warps of this CTA have written their row
    if (tid == 0) {
        unsigned int ticket = atomicAdd(&g_count, 1u);
        s_last = (ticket == (unsigned int)(gridDim.x - 1));
    }
    __syncthreads();
    if (!s_last) return;

    // 256 threads, 4 values each.
    float vals[DIM / BLOCK];
    float lmax = -INFINITY;
    #pragma unroll
    for (int k = 0; k < DIM / BLOCK; ++k) {
        const float v = g_z[tid + k * BLOCK];
        vals[k] = v;
        lmax = fmaxf(lmax, v);
    }
    #pragma unroll
    for (int o = 16; o > 0; o >>= 1)
        lmax = fmaxf(lmax, __shfl_xor_sync(0xffffffffu, lmax, o));
    if (lane == 0) s_max[warp] = lmax;
    __syncthreads();
    float bmax = s_max[0];
    #pragma unroll
    for (int w = 1; w < NWARP; ++w) bmax = fmaxf(bmax, s_max[w]);

    float lsum = 0.0f;
    #pragma unroll
    for (int k = 0; k < DIM / BLOCK; ++k)
        lsum += expf(vals[k] - bmax);
    #pragma unroll
    for (int o = 16; o > 0; o >>= 1)
        lsum += __shfl_xor_sync(0xffffffffu, lsum, o);
    if (lane == 0) s_sum[warp] = lsum;
    __syncthreads();
    float bsum = 0.0f;
    #pragma unroll
    for (int w = 0; w < NWARP; ++w) bsum += s_sum[w];

    const float lse = bmax + logf(bsum);
    #pragma unroll
    for (int k = 0; k < DIM / BLOCK; ++k)
        out[tid + k * BLOCK] = vals[k] - lse;

    // Reset ticket so every graph replay is identical.
    if (tid == 0) g_count = 0;
}

extern "C" void kernel_launch(void* const* d_in, const int* in_sizes, int n_in,
                              void* d_out, int out_size)
{
    // metadata order: input (int, unused), filters (DIM*VOCAB f32),
    //                 w_t (DIM*DIM f32), w_h (DIM*DIM f32)
    const float* filters = (const float*)d_in[1];
    const float* w_t     = (const float*)d_in[2];
    const float* w_h     = (const float*)d_in[3];
    float*       out     = (float*)d_out;

    const int vocab = in_sizes[1] / DIM;   // 50257

    embed_fused_kernel<<<GRID, BLOCK>>>(filters, w_t, w_h, out, vocab);
}